// round 7
// baseline (speedup 1.0000x reference)
#include <cuda_runtime.h>

// grid [2,160,160,160,3] float32
#define BB 2
#define NX 160
#define NY 160
#define NZ 160

#define TY 12
#define TZ 32
#define XSPLIT 6
#define XSTEPS 26                // 156 / XSPLIT
#define NTHREADS (TY*TZ)         // 384
#define NBLOCKS (5*13*BB*XSPLIT) // 780

#define RY (TY + 4)              // 16
#define RZ (TZ + 4)              // 36
#define SLICE (RY * RZ * 3)      // 1728 floats per staged slice
#define ROWW (NZ * 3)            // 480 floats per (b,x,y) row
#define CHUNKS (SLICE / 4)       // 432 16B chunks per slice
#define CPR (RZ * 3 / 4)         // 27 chunks per staged row

__device__ double g_be_sum;
__device__ unsigned int g_be_cnt;

__device__ __forceinline__ void cp16(unsigned int dst_smem, const float* src) {
    asm volatile("cp.async.cg.shared.global [%0], [%1], 16;" :: "r"(dst_smem), "l"(src));
}
__device__ __forceinline__ void cp_commit() {
    asm volatile("cp.async.commit_group;" ::: "memory");
}
__device__ __forceinline__ void cp_wait0() {
    asm volatile("cp.async.wait_group 0;" ::: "memory");
}
__device__ __forceinline__ void cp_wait1() {
    asm volatile("cp.async.wait_group 1;" ::: "memory");
}

__global__ __launch_bounds__(NTHREADS, 3)
void be_main_kernel(const float* __restrict__ g, float* __restrict__ out) {
    __shared__ float ring[6 * SLICE];       // 6-slot ring: read set {x..x+3} + 2 in flight
    __shared__ float warp_part[NTHREADS / 32];

    const int tz  = threadIdx.x;            // 0..31
    const int ty  = threadIdx.y;            // 0..11
    const int tid = ty * TZ + tz;

    const int cz  = blockIdx.x;             // 0..4
    const int cy  = blockIdx.y;             // 0..12
    const int b   = blockIdx.z / XSPLIT;
    const int seg = blockIdx.z % XSPLIT;

    const int z0 = 2 + cz * TZ;
    const int y0 = 2 + cy * TY;
    const int xs = 2 + seg * XSTEPS;

    const bool active = (z0 + tz) <= (NZ - 3);   // z in [2,157]

    // ---- 16B-chunk staging map (x-independent) ----
    const int zbase3 = (z0 - 2) * 3;
    int goffA, goffB;
    {
        int j = tid;
        int row = j / CPR, col = j - row * CPR;
        int o = zbase3 + col * 4;
        if (o > ROWW - 4) o = ROWW - 4;          // clamp: lands in unread halo slack
        goffA = row * ROWW + o;
        j = tid + NTHREADS;
        row = j / CPR; col = j - row * CPR;
        o = zbase3 + col * 4;
        if (o > ROWW - 4) o = ROWW - 4;
        goffB = row * ROWW + o;                   // used only when tid < CHUNKS-NTHREADS
    }

    const long long bbase = (long long)b * NX * NY * ROWW + (long long)(y0 - 2) * ROWW;
    const unsigned int ring_s = (unsigned int)__cvta_generic_to_shared(ring);

    auto issue_slice = [&](int gx, int slot) {
        const float* src = g + bbase + (long long)gx * (NY * ROWW);
        unsigned int sbase = ring_s + (unsigned int)(slot * SLICE) * 4u;
        cp16(sbase + (unsigned int)tid * 16u, src + goffA);
        if (tid < CHUNKS - NTHREADS)
            cp16(sbase + (unsigned int)(tid + NTHREADS) * 16u, src + goffB);
    };

    // ---- slot(x) = (x - xs + 2) mod 6 ----
    // prologue group 1: xs-2..xs+1 -> slots 0..3
    issue_slice(xs - 2, 0);
    issue_slice(xs - 1, 1);
    issue_slice(xs,     2);
    issue_slice(xs + 1, 3);
    cp_commit();
    // prologue group 2: xs+2 -> 4, xs+3 -> 5 (stays in flight during init)
    issue_slice(xs + 2, 4);
    issue_slice(xs + 3, 5);
    cp_commit();

    cp_wait1();                 // group 1 landed
    __syncthreads();

    const int off0 = ((ty + 2) * RZ + (tz + 2)) * 3;
    #define Y (RZ * 3)
    #define Zw 3

    // center delay lines
    float c0a, c0b, c0c, c0d, c0e;
    float c1p2, c1p1, c1z, c2p2, c2p1, c2z;
    // q delay lines for mixed x-derivatives
    float q2_xy0, q2_xy1, q2_xz0, q2_xz1, q2_xz2;
    float q1_xy0, q1_xy1, q1_xz0, q1_xz1, q1_xz2;
    {
        const float* s;
        s = ring + 3 * SLICE; c0a = s[off0]; c1p2 = s[off0 + 1]; c2p2 = s[off0 + 2]; // xs+1
        s = ring + 2 * SLICE; c0b = s[off0]; c1p1 = s[off0 + 1]; c2p1 = s[off0 + 2]; // xs
        q1_xy0 = s[off0 + Y]      - s[off0 - Y];
        q1_xy1 = s[off0 + Y + 1]  - s[off0 - Y + 1];
        q1_xz0 = s[off0 + Zw]     - s[off0 - Zw];
        q1_xz1 = s[off0 + Zw + 1] - s[off0 - Zw + 1];
        q1_xz2 = s[off0 + Zw + 2] - s[off0 - Zw + 2];
        s = ring + 1 * SLICE; c0c = s[off0];                                          // xs-1
        q2_xy0 = s[off0 + Y]      - s[off0 - Y];
        q2_xy1 = s[off0 + Y + 1]  - s[off0 - Y + 1];
        q2_xz0 = s[off0 + Zw]     - s[off0 - Zw];
        q2_xz1 = s[off0 + Zw + 1] - s[off0 - Zw + 1];
        q2_xz2 = s[off0 + Zw + 2] - s[off0 - Zw + 2];
        s = ring;             c0d = s[off0];                                          // xs-2 (slot 0)
        c0e = 0.f; c1z = 0.f; c2z = 0.f;
    }

    float acc = 0.0f;
    int gx4 = xs + 4;           // next slice to stage

    // One stencil step (no staging, no barrier — those live at superstep level).
    #define DO_STEP(S0i, SP1i, SP2i)                                              \
    {                                                                             \
        {                                                                         \
            const float* sp = ring + (SP2i) * SLICE;                              \
            float n0 = sp[off0], n1 = sp[off0 + 1], n2 = sp[off0 + 2];            \
            c0e = c0d; c0d = c0c; c0c = c0b; c0b = c0a; c0a = n0;                 \
            c1z = c1p1; c1p1 = c1p2; c1p2 = n1;                                   \
            c2z = c2p1; c2p1 = c2p2; c2p2 = n2;                                   \
        }                                                                         \
        const float* Sp1 = ring + (SP1i) * SLICE;                                 \
        const float qn_xy0 = Sp1[off0 + Y]      - Sp1[off0 - Y];                  \
        const float qn_xy1 = Sp1[off0 + Y + 1]  - Sp1[off0 - Y + 1];              \
        const float qn_xz0 = Sp1[off0 + Zw]     - Sp1[off0 - Zw];                 \
        const float qn_xz1 = Sp1[off0 + Zw + 1] - Sp1[off0 - Zw + 1];             \
        const float qn_xz2 = Sp1[off0 + Zw + 2] - Sp1[off0 - Zw + 2];             \
        if (active) {                                                             \
            const float* S0 = ring + (S0i) * SLICE;                               \
            const float dxx0 = c0e + c0a - 2.0f * c0c;                            \
            const float dyy0 = S0[off0 - 2*Y]      + S0[off0 + 2*Y]      - 2.0f * c0c; \
            const float dyy1 = S0[off0 - 2*Y + 1]  + S0[off0 + 2*Y + 1]  - 2.0f * c1z; \
            const float dzz0 = S0[off0 - 2*Zw]     + S0[off0 + 2*Zw]     - 2.0f * c0c; \
            const float dzz1 = S0[off0 - 2*Zw + 1] + S0[off0 + 2*Zw + 1] - 2.0f * c1z; \
            const float dzz2 = S0[off0 - 2*Zw + 2] + S0[off0 + 2*Zw + 2] - 2.0f * c2z; \
            const float dxy0 = qn_xy0 - q2_xy0;                                   \
            const float dxy1 = qn_xy1 - q2_xy1;                                   \
            const float dxz0 = qn_xz0 - q2_xz0;                                   \
            const float dxz1 = qn_xz1 - q2_xz1;                                   \
            const float dxz2 = qn_xz2 - q2_xz2;                                   \
            const float dyz0 = S0[off0 + Y + Zw]     - S0[off0 + Y - Zw]     - S0[off0 - Y + Zw]     + S0[off0 - Y - Zw];         \
            const float dyz1 = S0[off0 + Y + Zw + 1] - S0[off0 + Y - Zw + 1] - S0[off0 - Y + Zw + 1] + S0[off0 - Y - Zw + 1];     \
            const float dyz2 = S0[off0 + Y + Zw + 2] - S0[off0 + Y - Zw + 2] - S0[off0 - Y + Zw + 2] + S0[off0 - Y - Zw + 2];     \
            float v = dxx0 * dxx0;                                                \
            v = fmaf(2.0f * dyy0, dyy0, v);                                       \
            v = fmaf(2.0f * dzz0, dzz0, v);                                       \
            v = fmaf(3.0f * dxy0, dxy0, v);                                       \
            v = fmaf(3.0f * dxz0, dxz0, v);                                       \
            v = fmaf(4.0f * dyz0, dyz0, v);                                       \
            v = fmaf(dyy1, dyy1, v);                                              \
            v = fmaf(2.0f * dzz1, dzz1, v);                                       \
            v = fmaf(dxy1, dxy1, v);                                              \
            v = fmaf(2.0f * dxz1, dxz1, v);                                       \
            v = fmaf(3.0f * dyz1, dyz1, v);                                       \
            v = fmaf(dzz2, dzz2, v);                                              \
            v = fmaf(dxz2, dxz2, v);                                              \
            v = fmaf(dyz2, dyz2, v);                                              \
            acc += v;                                                             \
        }                                                                         \
        q2_xy0 = q1_xy0; q2_xy1 = q1_xy1;                                         \
        q2_xz0 = q1_xz0; q2_xz1 = q1_xz1; q2_xz2 = q1_xz2;                        \
        q1_xy0 = qn_xy0; q1_xy1 = qn_xy1;                                         \
        q1_xz0 = qn_xz0; q1_xz1 = qn_xz1; q1_xz2 = qn_xz2;                        \
    }

    // Superstep = 2 x-steps, one wait + one barrier, stage 2 slices into dead slots.
    // Slots: x->Ai, x+1->Bi, x+2->Ci, x+3->Di; stage x+4->Ei, x+5->Fi.
    #define SUPER(Ai, Bi, Ci, Di, Ei, Fi)                                         \
    {                                                                             \
        cp_wait0();                                                               \
        __syncthreads();                                                          \
        {                                                                         \
            int gA = gx4     > (NX - 1) ? (NX - 1) : gx4;                         \
            int gB = gx4 + 1 > (NX - 1) ? (NX - 1) : gx4 + 1;                     \
            issue_slice(gA, (Ei));                                                \
            issue_slice(gB, (Fi));                                                \
            cp_commit();                                                          \
            gx4 += 2;                                                             \
        }                                                                         \
        DO_STEP(Ai, Bi, Ci)                                                       \
        DO_STEP(Bi, Ci, Di)                                                       \
    }

    // 26 steps = 13 supersteps; slot pattern period 3 (13 = 4*3 + 1)
    #pragma unroll 1
    for (int it = 0; it < 4; ++it) {
        SUPER(2, 3, 4, 5, 0, 1);
        SUPER(4, 5, 0, 1, 2, 3);
        SUPER(0, 1, 2, 3, 4, 5);
    }
    SUPER(2, 3, 4, 5, 0, 1);    // superstep 12 (steps 24, 25)

    #undef SUPER
    #undef DO_STEP
    #undef Y
    #undef Zw

    // block reduction
    float v = acc;
    #pragma unroll
    for (int o = 16; o > 0; o >>= 1) v += __shfl_down_sync(0xffffffffu, v, o);
    if ((tid & 31) == 0) warp_part[tid >> 5] = v;
    __syncthreads();
    if (tid == 0) {
        float s = 0.0f;
        #pragma unroll
        for (int w = 0; w < NTHREADS / 32; ++w) s += warp_part[w];
        atomicAdd(&g_be_sum, (double)s);
        __threadfence();
        unsigned int t = atomicAdd(&g_be_cnt, 1u);
        if (t == NBLOCKS - 1) {
            double total = atomicAdd(&g_be_sum, 0.0);   // ordered read of final sum
            const double n = (double)BB * 156.0 * 156.0 * 156.0 * 3.0;
            out[0] = (float)(total / (16.0 * n));
            g_be_cnt = 0;        // reset for next (graph-replayed) launch
            g_be_sum = 0.0;
        }
    }
}

extern "C" void kernel_launch(void* const* d_in, const int* in_sizes, int n_in,
                              void* d_out, int out_size) {
    const float* grid = (const float*)d_in[0];
    float* out = (float*)d_out;

    dim3 blk(TZ, TY, 1);
    dim3 grd(5, 13, BB * XSPLIT);
    be_main_kernel<<<grd, blk>>>(grid, out);
}

// round 8
// speedup vs baseline: 1.0280x; 1.0280x over previous
#include <cuda_runtime.h>

// grid [2,160,160,160,3] float32
#define BB 2
#define NX 160
#define NY 160
#define NZ 160

#define TY 12
#define NCHUNK 6                  // z chunks, 28 outputs each (168 >= 156)
#define XSPLIT 6
#define XSTEPS 26                 // 156 / XSPLIT
#define NTHREADS (TY*32)          // 384
#define NBLOCKS (NCHUNK*13*BB*XSPLIT) // 936

#define RY (TY + 4)               // 16
#define RZ_ST 32                  // staged z per slice (z0-2 .. z0+29)
#define SLICE (RY * RZ_ST * 3)    // 1536 floats
#define ROWW (NZ * 3)             // 480 floats per (b,x,y) row
#define CPR (RZ_ST * 3 / 4)       // 24 16B chunks per staged row
#define CHUNKS (RY * CPR)         // 384 == NTHREADS: one cp16 per thread

__device__ double g_be_sum;
__device__ unsigned int g_be_cnt;

__device__ __forceinline__ void cp16(unsigned int dst_smem, const float* src) {
    asm volatile("cp.async.cg.shared.global [%0], [%1], 16;" :: "r"(dst_smem), "l"(src));
}
__device__ __forceinline__ void cp_commit() {
    asm volatile("cp.async.commit_group;" ::: "memory");
}
__device__ __forceinline__ void cp_wait0() {
    asm volatile("cp.async.wait_group 0;" ::: "memory");
}
__device__ __forceinline__ void cp_wait1() {
    asm volatile("cp.async.wait_group 1;" ::: "memory");
}

#define SHUP(v)  __shfl_up_sync(0xffffffffu, (v), 1)
#define SHDN(v)  __shfl_down_sync(0xffffffffu, (v), 1)
#define SHUP2(v) __shfl_up_sync(0xffffffffu, (v), 2)
#define SHDN2(v) __shfl_down_sync(0xffffffffu, (v), 2)

__global__ __launch_bounds__(NTHREADS, 3)
void be_main_kernel(const float* __restrict__ g, float* __restrict__ out) {
    __shared__ float ring[5 * SLICE];
    __shared__ float warp_part[NTHREADS / 32];

    const int tz  = threadIdx.x;            // 0..31 (lane)
    const int ty  = threadIdx.y;            // 0..11
    const int tid = ty * 32 + tz;

    const int cz  = blockIdx.x;             // 0..5   z chunk (28 outputs each)
    const int cy  = blockIdx.y;             // 0..12
    const int b   = blockIdx.z / XSPLIT;
    const int seg = blockIdx.z % XSPLIT;

    const int z0 = 2 + cz * 28;             // first output z of this chunk
    const int y0 = 2 + cy * TY;
    const int xs = 2 + seg * XSTEPS;

    // lane l holds center z = z0 - 2 + l; outputs come from lanes 2..29
    const int zc = z0 - 2 + tz;
    const bool active = (tz >= 2) && (tz <= 29) && (zc <= NZ - 3);

    // ---- staging map: exactly one 16B chunk per thread ----
    const int zbase3 = (z0 - 2) * 3;        // = 84*cz, 16B-aligned
    int goff;
    {
        int row = tid / CPR, col = tid - row * CPR;
        int o = zbase3 + col * 4;
        if (o > ROWW - 4) o = ROWW - 4;     // clamp: lands in unread lane-halo slack
        goff = row * ROWW + o;
    }

    const long long bbase = (long long)b * NX * NY * ROWW + (long long)(y0 - 2) * ROWW;
    const unsigned int ring_s = (unsigned int)__cvta_generic_to_shared(ring);

    auto issue_slice = [&](int gx, int slot) {
        const float* src = g + bbase + (long long)gx * (NY * ROWW);
        cp16(ring_s + (unsigned int)(slot * SLICE) * 4u + (unsigned int)tid * 16u,
             src + goff);
    };

    // ---- slot(x) = (x - xs + 2) mod 5; prologue: xs-2..xs+1 -> slots 0..3 ----
    issue_slice(xs - 2, 0);
    issue_slice(xs - 1, 1);
    issue_slice(xs,     2);
    issue_slice(xs + 1, 3);
    cp_commit();
    cp_wait0();
    __syncthreads();

    const int off0 = ((ty + 2) * RZ_ST + tz) * 3;
    #define Y (RZ_ST * 3)
    #define Zw 3

    // center delay lines: c0 x+2..x-2; c1,c2 x+2..x
    float c0a, c0b, c0c, c0d, c0e;
    float c1p2, c1p1, c1z, c2p2, c2p1, c2z;
    // q delay lines: q(s) = S_s[+off] - S_s[-off]
    float q2_xy0, q2_xy1, q2_xz0, q2_xz1, q2_xz2;
    float q1_xy0, q1_xy1, q1_xy2, q1_xz0, q1_xz1, q1_xz2;
    {
        const float* s;
        s = ring + 3 * SLICE; c0a = s[off0]; c1p2 = s[off0 + 1]; c2p2 = s[off0 + 2]; // xs+1
        s = ring + 2 * SLICE; c0b = s[off0]; c1p1 = s[off0 + 1]; c2p1 = s[off0 + 2]; // xs
        q1_xy0 = s[off0 + Y]      - s[off0 - Y];
        q1_xy1 = s[off0 + Y + 1]  - s[off0 - Y + 1];
        q1_xy2 = s[off0 + Y + 2]  - s[off0 - Y + 2];
        q1_xz0 = s[off0 + Zw]     - s[off0 - Zw];
        q1_xz1 = s[off0 + Zw + 1] - s[off0 - Zw + 1];
        q1_xz2 = s[off0 + Zw + 2] - s[off0 - Zw + 2];
        s = ring + 1 * SLICE; c0c = s[off0];                                          // xs-1
        q2_xy0 = s[off0 + Y]      - s[off0 - Y];
        q2_xy1 = s[off0 + Y + 1]  - s[off0 - Y + 1];
        q2_xz0 = s[off0 + Zw]     - s[off0 - Zw];
        q2_xz1 = s[off0 + Zw + 1] - s[off0 - Zw + 1];
        q2_xz2 = s[off0 + Zw + 2] - s[off0 - Zw + 2];
        s = ring;             c0d = s[off0];                                          // xs-2
        c0e = 0.f; c1z = 0.f; c2z = 0.f;
    }
    __syncthreads();            // init reads done before slot 0/4 reuse

    // pipeline: xs+2 -> slot 4, xs+3 -> slot 0 (two groups in flight)
    issue_slice(xs + 2, 4); cp_commit();
    issue_slice(xs + 3, 0); cp_commit();

    float acc = 0.0f;
    int gx4 = xs + 4;

    #define DO_STEP(SM1i, S0i, SP1i, SP2i)                                        \
    {                                                                             \
        cp_wait1();                                                               \
        __syncthreads();                                                          \
        {                                                                         \
            int gxs = gx4 > (NX - 1) ? (NX - 1) : gx4;                            \
            issue_slice(gxs, (SM1i)); cp_commit(); ++gx4;                         \
        }                                                                         \
        {                                                                         \
            const float* sp = ring + (SP2i) * SLICE;                              \
            float n0 = sp[off0], n1 = sp[off0 + 1], n2 = sp[off0 + 2];            \
            c0e = c0d; c0d = c0c; c0c = c0b; c0b = c0a; c0a = n0;                 \
            c1z = c1p1; c1p1 = c1p2; c1p2 = n1;                                   \
            c2z = c2p1; c2p1 = c2p2; c2p2 = n2;                                   \
        }                                                                         \
        const float* Sp1 = ring + (SP1i) * SLICE;                                 \
        const float qn_xy0 = Sp1[off0 + Y]     - Sp1[off0 - Y];                   \
        const float qn_xy1 = Sp1[off0 + Y + 1] - Sp1[off0 - Y + 1];               \
        const float qn_xy2 = Sp1[off0 + Y + 2] - Sp1[off0 - Y + 2];               \
        const float qn_xz0 = SHDN(c0b)  - SHUP(c0b);                              \
        const float qn_xz1 = SHDN(c1p1) - SHUP(c1p1);                             \
        const float qn_xz2 = SHDN(c2p1) - SHUP(c2p1);                             \
        const float dyz0 = SHDN(q1_xy0) - SHUP(q1_xy0);                           \
        const float dyz1 = SHDN(q1_xy1) - SHUP(q1_xy1);                           \
        const float dyz2 = SHDN(q1_xy2) - SHUP(q1_xy2);                           \
        const float dzz0 = SHUP2(c0c) + SHDN2(c0c) - 2.0f * c0c;                  \
        const float dzz1 = SHUP2(c1z) + SHDN2(c1z) - 2.0f * c1z;                  \
        const float dzz2 = SHUP2(c2z) + SHDN2(c2z) - 2.0f * c2z;                  \
        if (active) {                                                             \
            const float* S0 = ring + (S0i) * SLICE;                               \
            const float dxx0 = c0e + c0a - 2.0f * c0c;                            \
            const float dyy0 = S0[off0 - 2*Y]     + S0[off0 + 2*Y]     - 2.0f * c0c; \
            const float dyy1 = S0[off0 - 2*Y + 1] + S0[off0 + 2*Y + 1] - 2.0f * c1z; \
            const float dxy0 = qn_xy0 - q2_xy0;                                   \
            const float dxy1 = qn_xy1 - q2_xy1;                                   \
            const float dxz0 = qn_xz0 - q2_xz0;                                   \
            const float dxz1 = qn_xz1 - q2_xz1;                                   \
            const float dxz2 = qn_xz2 - q2_xz2;                                   \
            float v = dxx0 * dxx0;                                                \
            v = fmaf(2.0f * dyy0, dyy0, v);                                       \
            v = fmaf(2.0f * dzz0, dzz0, v);                                       \
            v = fmaf(3.0f * dxy0, dxy0, v);                                       \
            v = fmaf(3.0f * dxz0, dxz0, v);                                       \
            v = fmaf(4.0f * dyz0, dyz0, v);                                       \
            v = fmaf(dyy1, dyy1, v);                                              \
            v = fmaf(2.0f * dzz1, dzz1, v);                                       \
            v = fmaf(dxy1, dxy1, v);                                              \
            v = fmaf(2.0f * dxz1, dxz1, v);                                       \
            v = fmaf(3.0f * dyz1, dyz1, v);                                       \
            v = fmaf(dzz2, dzz2, v);                                              \
            v = fmaf(dxz2, dxz2, v);                                              \
            v = fmaf(dyz2, dyz2, v);                                              \
            acc += v;                                                             \
        }                                                                         \
        q2_xy0 = q1_xy0; q2_xy1 = q1_xy1;                                         \
        q2_xz0 = q1_xz0; q2_xz1 = q1_xz1; q2_xz2 = q1_xz2;                        \
        q1_xy0 = qn_xy0; q1_xy1 = qn_xy1; q1_xy2 = qn_xy2;                        \
        q1_xz0 = qn_xz0; q1_xz1 = qn_xz1; q1_xz2 = qn_xz2;                        \
    }

    // 26 steps = 5 x 5 + 1 tail; slot pattern period 5 (all literals)
    #pragma unroll 1
    for (int it = 0; it < 5; ++it) {
        DO_STEP(1, 2, 3, 4);
        DO_STEP(2, 3, 4, 0);
        DO_STEP(3, 4, 0, 1);
        DO_STEP(4, 0, 1, 2);
        DO_STEP(0, 1, 2, 3);
    }
    DO_STEP(1, 2, 3, 4);        // step 25

    #undef DO_STEP
    #undef Y
    #undef Zw

    // block reduction
    float v = acc;
    #pragma unroll
    for (int o = 16; o > 0; o >>= 1) v += __shfl_down_sync(0xffffffffu, v, o);
    if ((tid & 31) == 0) warp_part[tid >> 5] = v;
    __syncthreads();
    if (tid == 0) {
        float s = 0.0f;
        #pragma unroll
        for (int w = 0; w < NTHREADS / 32; ++w) s += warp_part[w];
        atomicAdd(&g_be_sum, (double)s);
        __threadfence();
        unsigned int t = atomicAdd(&g_be_cnt, 1u);
        if (t == NBLOCKS - 1) {
            double total = atomicAdd(&g_be_sum, 0.0);   // ordered read of final sum
            const double n = (double)BB * 156.0 * 156.0 * 156.0 * 3.0;
            out[0] = (float)(total / (16.0 * n));
            g_be_cnt = 0;        // reset for next (graph-replayed) launch
            g_be_sum = 0.0;
        }
    }
}

extern "C" void kernel_launch(void* const* d_in, const int* in_sizes, int n_in,
                              void* d_out, int out_size) {
    const float* grid = (const float*)d_in[0];
    float* out = (float*)d_out;

    dim3 blk(32, TY, 1);
    dim3 grd(NCHUNK, 13, BB * XSPLIT);
    be_main_kernel<<<grd, blk>>>(grid, out);
}